// round 2
// baseline (speedup 1.0000x reference)
#include <cuda_runtime.h>
#include <math.h>

#define B_   2
#define L_   4096
#define D_   1024
#define H_   16
#define HD_  64
#define CH_  128
#define NCH_ 32          // L_/CH_
#define BH_  32          // B_*H_
#define TOK_ 8192        // B_*L_
#define GTOK_ 8          // tokens per gates block

// ---------------- scratch (device globals; no allocation) ----------------
__device__ float g_q [BH_*L_*HD_];
__device__ float g_k [BH_*L_*HD_];
__device__ float g_v [BH_*L_*HD_];
__device__ float g_ks[BH_*L_*HD_];
__device__ float g_vs[BH_*L_*HD_];
__device__ float g_state[2*BH_*NCH_*HD_*HD_];
__device__ float g_oc[TOK_*D_];
__device__ float g_beta[BH_*L_];
__device__ float g_fd [BH_*L_];
__device__ float g_sd [BH_*L_];
__device__ float g_fg [BH_*L_];
__device__ float g_sg [BH_*L_];
__device__ float g_psi[BH_*L_];
__device__ float g_dff[BH_*NCH_];
__device__ float g_dfs[BH_*NCH_];
__device__ float g_WT [80*D_];   // transposed gate weights [o=g*16+h][D]

__device__ __forceinline__ float sigm(float x){ return 1.0f/(1.0f+expf(-x)); }

// ---------------- transpose gate weights ----------------
__global__ void wt_kernel(const float* __restrict__ Wb,  const float* __restrict__ Wfd,
                          const float* __restrict__ Wsd, const float* __restrict__ Wfg,
                          const float* __restrict__ Wsg){
    int o = blockIdx.x;           // 0..79
    int g = o >> 4, h = o & 15;
    const float* W = (g==0)?Wb:(g==1)?Wfd:(g==2)?Wsd:(g==3)?Wfg:Wsg;
    for(int i = threadIdx.x; i < D_; i += blockDim.x)
        g_WT[o*D_ + i] = W[i*H_ + h];
}

// ---------------- big SGEMM: 128x128 tile, BK=8, 8x8/thread ----------------
// JOB 0/1/2 : C = silu(A @ W) scattered to head layout into g_q/g_k/g_v (A = x)
// JOB 3     : C = g_oc @ W, plain row-major into Cout (final projection)
template<int JOB>
__global__ __launch_bounds__(256) void sgemm_kernel(const float* __restrict__ Ain,
                                                    const float* __restrict__ W,
                                                    float* __restrict__ Cout){
    const int M = TOK_, N = D_, K = D_;
    __shared__ float As[8][128];
    __shared__ float Bs[8][128];
    const float* A = (JOB==3) ? &g_oc[0] : Ain;

    const int tid = threadIdx.x, ty = tid >> 4, tx = tid & 15;
    const int rowBase = blockIdx.y * 128, colBase = blockIdx.x * 128;
    const int arow = tid >> 1,  acol = (tid & 1) * 4;
    const int brow = tid >> 5,  bcol = (tid & 31) * 4;
    const float* Ap = A + (size_t)(rowBase + arow) * K + acol;
    const float* Bp = W + (size_t)brow * N + colBase + bcol;

    float acc[8][8];
    #pragma unroll
    for(int i=0;i<8;i++)
        #pragma unroll
        for(int j=0;j<8;j++) acc[i][j]=0.f;

    for(int k0 = 0; k0 < K; k0 += 8){
        float4 a4 = *(const float4*)(Ap + k0);
        float4 b4 = *(const float4*)(Bp + (size_t)k0 * N);
        As[acol+0][arow]=a4.x; As[acol+1][arow]=a4.y;
        As[acol+2][arow]=a4.z; As[acol+3][arow]=a4.w;
        *(float4*)&Bs[brow][bcol] = b4;
        __syncthreads();
        #pragma unroll
        for(int kk=0;kk<8;kk++){
            float af[8], bf[8];
            *(float4*)&af[0]=*(float4*)&As[kk][ty*8];
            *(float4*)&af[4]=*(float4*)&As[kk][ty*8+4];
            *(float4*)&bf[0]=*(float4*)&Bs[kk][tx*8];
            *(float4*)&bf[4]=*(float4*)&Bs[kk][tx*8+4];
            #pragma unroll
            for(int i=0;i<8;i++)
                #pragma unroll
                for(int j=0;j<8;j++) acc[i][j] += af[i]*bf[j];
        }
        __syncthreads();
    }

    if(JOB == 3){
        #pragma unroll
        for(int i=0;i<8;i++){
            float* Cp = Cout + (size_t)(rowBase + ty*8 + i) * N + colBase + tx*8;
            *(float4*)Cp     = make_float4(acc[i][0],acc[i][1],acc[i][2],acc[i][3]);
            *(float4*)(Cp+4) = make_float4(acc[i][4],acc[i][5],acc[i][6],acc[i][7]);
        }
    } else {
        float* Dst = (JOB==0) ? &g_q[0] : (JOB==1) ? &g_k[0] : &g_v[0];
        #pragma unroll
        for(int i=0;i<8;i++){
            int r = rowBase + ty*8 + i;
            int b = r >> 12, l = r & (L_-1);
            #pragma unroll
            for(int j=0;j<8;j++){
                int c = colBase + tx*8 + j;
                int h = c >> 6, d = c & 63;
                float x = acc[i][j];
                Dst[(((size_t)(b*H_ + h)*L_ + l) << 6) + d] = x * sigm(x);
            }
        }
    }
}

// ---------------- gate projections: 5 gates x 16 heads per token ----------------
__global__ __launch_bounds__(256) void gates_kernel(const float* __restrict__ x,
                                                    const float* __restrict__ fdb,
                                                    const float* __restrict__ sdb){
    __shared__ float xs[GTOK_][D_];         // 32 KB
    int t0 = blockIdx.x * GTOK_;
    for(int i = threadIdx.x; i < GTOK_*D_/4; i += 256)
        ((float4*)&xs[0][0])[i] = ((const float4*)(x + (size_t)t0 * D_))[i];
    __syncthreads();
    int warp = threadIdx.x >> 5, lane = threadIdx.x & 31;
    for(int o = warp; o < 80; o += 8){
        int g = o >> 4, h = o & 15;
        const float* Wt = &g_WT[o*D_];
        float wreg[32];
        #pragma unroll
        for(int j=0;j<32;j++) wreg[j] = Wt[j*32 + lane];
        float accv[GTOK_];
        #pragma unroll
        for(int tt=0;tt<GTOK_;tt++) accv[tt]=0.f;
        #pragma unroll
        for(int j=0;j<32;j++){
            float w = wreg[j];
            #pragma unroll
            for(int tt=0;tt<GTOK_;tt++) accv[tt] += xs[tt][j*32+lane] * w;
        }
        #pragma unroll
        for(int tt=0;tt<GTOK_;tt++){
            float s = accv[tt];
            #pragma unroll
            for(int off=16;off;off>>=1) s += __shfl_xor_sync(0xffffffffu, s, off);
            if(lane == 0){
                int t = t0 + tt, b = t >> 12, l = t & (L_-1);
                float bias = (g==1)?fdb[h] : (g==2)?sdb[h] : 0.f;
                float val = sigm(s + bias);
                int idx = (b*H_ + h)*L_ + l;
                if(g==0) g_beta[idx]=val; else if(g==1) g_fd[idx]=val;
                else if(g==2) g_sd[idx]=val; else if(g==3) g_fg[idx]=val;
                else g_sg[idx]=val;
            }
        }
    }
}

// ---------------- per-token prep: beta, psi, surprise, decays, chunk means ----------------
__global__ __launch_bounds__(128) void prep_kernel(){
    __shared__ float fw[CH_], sw[CH_];
    int bh = blockIdx.x >> 5, c = blockIdx.x & 31;
    int t = threadIdx.x;
    int gidx = bh*L_ + c*CH_ + t;
    size_t base = (size_t)gidx * HD_;
    float beta = g_beta[gidx];

    float kv=0.f, kk=0.f, vv=0.f;
    #pragma unroll 4
    for(int d4=0; d4<HD_/4; d4++){
        float4 k4 = *(const float4*)(g_k + base + d4*4);
        float4 v4 = *(const float4*)(g_v + base + d4*4);
        kv += k4.x*v4.x + k4.y*v4.y + k4.z*v4.z + k4.w*v4.w;
        kk += k4.x*k4.x + k4.y*k4.y + k4.z*k4.z + k4.w*k4.w;
        vv += v4.x*v4.x + v4.y*v4.y + v4.z*v4.z + v4.w*v4.w;
    }
    float b2 = beta*beta;
    float nk = sqrtf(kk*b2) + 1e-8f;
    float nv = sqrtf(vv*b2) + 1e-8f;
    float psi_raw = fabsf(kv*b2) / (nk*nv);
    float psi  = sigm(3.0f * psi_raw);
    float surp = sigm(10.0f * (psi - 0.5f));
    g_psi[gidx] = psi;
    fw[t] = g_fd[gidx] * (1.0f - 0.10f*psi);
    sw[t] = g_sd[gidx] * (1.0f - 0.05f*psi);

    #pragma unroll 4
    for(int d4=0; d4<HD_/4; d4++){
        float4 k4 = *(const float4*)(g_k + base + d4*4);
        float4 v4 = *(const float4*)(g_v + base + d4*4);
        k4.x*=beta; k4.y*=beta; k4.z*=beta; k4.w*=beta;
        v4.x*=beta; v4.y*=beta; v4.z*=beta; v4.w*=beta;
        *(float4*)(g_k + base + d4*4) = k4;
        *(float4*)(g_v + base + d4*4) = v4;
        float4 k5 = make_float4(k4.x*surp,k4.y*surp,k4.z*surp,k4.w*surp);
        float4 v5 = make_float4(v4.x*surp,v4.y*surp,v4.z*surp,v4.w*surp);
        *(float4*)(g_ks + base + d4*4) = k5;
        *(float4*)(g_vs + base + d4*4) = v5;
    }
    __syncthreads();
    for(int off=64; off; off>>=1){
        if(t < off){ fw[t] += fw[t+off]; sw[t] += sw[t+off]; }
        __syncthreads();
    }
    if(t == 0){
        g_dff[blockIdx.x] = powf(fw[0] * (1.0f/CH_), (float)CH_);
        g_dfs[blockIdx.x] = powf(sw[0] * (1.0f/CH_), (float)CH_);
    }
}

// ---------------- serial state scan: state[d][e], 64 blocks (pass,bh) ----------------
__global__ __launch_bounds__(256) void scan_kernel(){
    __shared__ float ksm[64][HD_];   // 16 KB
    __shared__ float vsm[64][HD_];   // 16 KB
    int pass = blockIdx.x >> 5, bh = blockIdx.x & 31;
    const float* kp  = pass ? &g_ks[0] : &g_k[0];
    const float* vp  = pass ? &g_vs[0] : &g_v[0];
    const float* dfp = pass ? &g_dfs[0] : &g_dff[0];
    int tid = threadIdx.x, ty = tid >> 4, tx = tid & 15;
    float st[4][4];
    #pragma unroll
    for(int i=0;i<4;i++)
        #pragma unroll
        for(int j=0;j<4;j++) st[i][j]=0.f;
    float* outp = &g_state[0] + (size_t)blockIdx.x * NCH_ * (HD_*HD_);

    for(int c = 0; c < NCH_; c++){
        float df = dfp[bh*NCH_ + c];
        #pragma unroll
        for(int i=0;i<4;i++)
            #pragma unroll
            for(int j=0;j<4;j++) st[i][j] *= df;
        #pragma unroll 1
        for(int half = 0; half < 2; half++){
            size_t base = ((size_t)bh*L_ + c*CH_ + half*64) * HD_;
            __syncthreads();
            for(int i = tid; i < 64*HD_/4; i += 256){
                ((float4*)&ksm[0][0])[i] = ((const float4*)(kp + base))[i];
                ((float4*)&vsm[0][0])[i] = ((const float4*)(vp + base))[i];
            }
            __syncthreads();
            #pragma unroll 4
            for(int l = 0; l < 64; l++){
                float4 v4 = *(float4*)&vsm[l][ty*4];
                float4 k4 = *(float4*)&ksm[l][tx*4];
                st[0][0]+=v4.x*k4.x; st[0][1]+=v4.x*k4.y; st[0][2]+=v4.x*k4.z; st[0][3]+=v4.x*k4.w;
                st[1][0]+=v4.y*k4.x; st[1][1]+=v4.y*k4.y; st[1][2]+=v4.y*k4.z; st[1][3]+=v4.y*k4.w;
                st[2][0]+=v4.z*k4.x; st[2][1]+=v4.z*k4.y; st[2][2]+=v4.z*k4.z; st[2][3]+=v4.z*k4.w;
                st[3][0]+=v4.w*k4.x; st[3][1]+=v4.w*k4.y; st[3][2]+=v4.w*k4.z; st[3][3]+=v4.w*k4.w;
            }
        }
        float* sp = outp + (size_t)c * (HD_*HD_);
        #pragma unroll
        for(int i=0;i<4;i++)
            *(float4*)(sp + (ty*4+i)*HD_ + tx*4) =
                make_float4(st[i][0], st[i][1], st[i][2], st[i][3]);
    }
}

// ---------------- per-chunk output: o = q @ state(fast/slow), gated combine ----------------
__global__ __launch_bounds__(256) void o_kernel(){
    __shared__ float qsm[CH_][HD_];   // 32 KB
    __shared__ float stm[HD_][HD_];   // 16 KB
    int bh = blockIdx.x >> 5, c = blockIdx.x & 31;
    int b = bh >> 4, h = bh & 15;
    int tid = threadIdx.x, ly = tid >> 4, dx = tid & 15;
    size_t qbase = ((size_t)bh*L_ + c*CH_) * HD_;
    for(int i = tid; i < CH_*HD_/4; i += 256)
        ((float4*)&qsm[0][0])[i] = ((const float4*)(&g_q[0] + qbase))[i];

    float accf[8][4], accs[8][4];
    // ---- fast pass ----
    {
        size_t sb = ((size_t)bh*NCH_ + c) * (HD_*HD_);
        for(int i = tid; i < HD_*HD_/4; i += 256)
            ((float4*)&stm[0][0])[i] = ((const float4*)(&g_state[0] + sb))[i];
        __syncthreads();
        #pragma unroll
        for(int i=0;i<8;i++){ accf[i][0]=0;accf[i][1]=0;accf[i][2]=0;accf[i][3]=0; }
        for(int d = 0; d < HD_; d++){
            float4 s4 = *(float4*)&stm[d][dx*4];
            #pragma unroll
            for(int i=0;i<8;i++){
                float qv = qsm[ly*8+i][d];
                accf[i][0]+=qv*s4.x; accf[i][1]+=qv*s4.y;
                accf[i][2]+=qv*s4.z; accf[i][3]+=qv*s4.w;
            }
        }
        __syncthreads();
    }
    // ---- slow pass ----
    {
        size_t sb = ((size_t)(BH_ + bh)*NCH_ + c) * (HD_*HD_);
        for(int i = tid; i < HD_*HD_/4; i += 256)
            ((float4*)&stm[0][0])[i] = ((const float4*)(&g_state[0] + sb))[i];
        __syncthreads();
        #pragma unroll
        for(int i=0;i<8;i++){ accs[i][0]=0;accs[i][1]=0;accs[i][2]=0;accs[i][3]=0; }
        for(int d = 0; d < HD_; d++){
            float4 s4 = *(float4*)&stm[d][dx*4];
            #pragma unroll
            for(int i=0;i<8;i++){
                float qv = qsm[ly*8+i][d];
                accs[i][0]+=qv*s4.x; accs[i][1]+=qv*s4.y;
                accs[i][2]+=qv*s4.z; accs[i][3]+=qv*s4.w;
            }
        }
    }
    // ---- gated combine -> token-major [B,L,D] ----
    #pragma unroll
    for(int i=0;i<8;i++){
        int l = ly*8 + i;
        int gidx = bh*L_ + c*CH_ + l;
        float psi = g_psi[gidx];
        float a   = 0.5f + 0.3f*psi;
        float fa  = a * g_fg[gidx];
        float sa  = (1.0f - a) * g_sg[gidx];
        float4 o;
        o.x = fa*accf[i][0] + sa*accs[i][0];
        o.y = fa*accf[i][1] + sa*accs[i][1];
        o.z = fa*accf[i][2] + sa*accs[i][2];
        o.w = fa*accf[i][3] + sa*accs[i][3];
        *(float4*)(&g_oc[0] + ((size_t)(b*L_ + c*CH_ + l))*D_ + h*HD_ + dx*4) = o;
    }
}

// ---------------- launch ----------------
extern "C" void kernel_launch(void* const* d_in, const int* in_sizes, int n_in,
                              void* d_out, int out_size){
    const float* x   = (const float*)d_in[0];
    const float* Wq  = (const float*)d_in[1];
    const float* Wk  = (const float*)d_in[2];
    const float* Wv  = (const float*)d_in[3];
    const float* Wb  = (const float*)d_in[4];
    const float* Wfd = (const float*)d_in[5];
    const float* fdb = (const float*)d_in[6];
    const float* Wsd = (const float*)d_in[7];
    const float* sdb = (const float*)d_in[8];
    const float* Wfg = (const float*)d_in[9];
    const float* Wsg = (const float*)d_in[10];
    const float* Wo  = (const float*)d_in[11];
    float* out = (float*)d_out;

    dim3 gg(D_/128, TOK_/128);   // (8, 64)

    wt_kernel<<<80, 256>>>(Wb, Wfd, Wsd, Wfg, Wsg);
    sgemm_kernel<0><<<gg, 256>>>(x, Wq, nullptr);   // q = silu(x@Wq) -> g_q
    sgemm_kernel<1><<<gg, 256>>>(x, Wk, nullptr);   // k -> g_k
    sgemm_kernel<2><<<gg, 256>>>(x, Wv, nullptr);   // v -> g_v
    gates_kernel<<<TOK_/GTOK_, 256>>>(x, fdb, sdb);
    prep_kernel<<<BH_*NCH_, 128>>>();
    scan_kernel<<<2*BH_, 256>>>();
    o_kernel<<<BH_*NCH_, 256>>>();
    sgemm_kernel<3><<<gg, 256>>>(nullptr, Wo, out); // out = g_oc @ Wo
}

// round 6
// speedup vs baseline: 1.3117x; 1.3117x over previous
#include <cuda_runtime.h>
#include <cuda_bf16.h>
#include <mma.h>
#include <math.h>
#include <stdint.h>

using namespace nvcuda;

#define B_   2
#define L_   4096
#define D_   1024
#define H_   16
#define HD_  64
#define CH_  128
#define NCH_ 32
#define BH_  32
#define TOK_ 8192
#define GTOK_ 8

// ---------------- scratch (device globals; no allocation) ----------------
__device__ float g_q [BH_*L_*HD_];
__device__ float g_k [BH_*L_*HD_];
__device__ float g_v [BH_*L_*HD_];
__device__ float g_ks[BH_*L_*HD_];
__device__ float g_vs[BH_*L_*HD_];
__device__ float g_state[2*BH_*NCH_*HD_*HD_];
__device__ float g_oc[TOK_*D_];
__device__ float g_beta[BH_*L_];
__device__ float g_fd [BH_*L_];
__device__ float g_sd [BH_*L_];
__device__ float g_fg [BH_*L_];
__device__ float g_sg [BH_*L_];
__device__ float g_psi[BH_*L_];
__device__ float g_dff[BH_*NCH_];
__device__ float g_dfs[BH_*NCH_];
__device__ float g_WT [80*D_];

__device__ __forceinline__ float sigm(float x){ return 1.0f/(1.0f+expf(-x)); }

// ---------------- transpose gate weights ----------------
__global__ void wt_kernel(const float* __restrict__ Wb,  const float* __restrict__ Wfd,
                          const float* __restrict__ Wsd, const float* __restrict__ Wfg,
                          const float* __restrict__ Wsg){
    int o = blockIdx.x;
    int g = o >> 4, h = o & 15;
    const float* W = (g==0)?Wb:(g==1)?Wfd:(g==2)?Wsd:(g==3)?Wfg:Wsg;
    for(int i = threadIdx.x; i < D_; i += blockDim.x)
        g_WT[o*D_ + i] = W[i*H_ + h];
}

// ---------------- WMMA bf16 split-GEMM: C = A(f32) @ W(f32), 3-term hi/lo ----------------
// C[8192x1024]; 128x128 tile/CTA, BK=32, in-kernel f32->bf16 hi/lo conversion.
// acc += Ah*Wh + Ah*Wl + Al*Wh  (error ~2^-16 relative, well under 1e-3)
// 8 warps, each 64x32 output (4x2 wmma 16x16x16 frags).
// JOB 0/1/2: A=x, epilogue silu -> g_q/g_k/g_v head layout.  JOB 3: A=g_oc -> Cout.
template<int JOB>
__global__ __launch_bounds__(256) void wgemm_kernel(const float* __restrict__ Ain,
                                                    const float* __restrict__ W,
                                                    float* __restrict__ Cout){
    __shared__ __align__(32) __nv_bfloat16 sAh[128][40];   // 10240 B
    __shared__ __align__(32) __nv_bfloat16 sAl[128][40];   // 10240 B
    __shared__ __align__(32) __nv_bfloat16 sWh[32][136];   //  8704 B
    __shared__ __align__(32) __nv_bfloat16 sWl[32][136];   //  8704 B
    const float* A = (JOB==3) ? &g_oc[0] : Ain;

    int tid = threadIdx.x, warp = tid >> 5;
    int wm = (warp >> 2) * 64, wn = (warp & 3) * 32;
    int rowBase = blockIdx.y * 128, colBase = blockIdx.x * 128;

    // staging coords
    int ar = tid >> 1,  ac = (tid & 1) * 16;    // A: 128 rows x 32 k, 16 floats/thread
    int wr = tid >> 3,  wc = (tid & 7) * 16;    // W: 32 k x 128 n,  16 floats/thread

    wmma::fragment<wmma::accumulator,16,16,16,float> cf[4][2];
    #pragma unroll
    for(int mi=0;mi<4;mi++)
        #pragma unroll
        for(int nj=0;nj<2;nj++) wmma::fill_fragment(cf[mi][nj], 0.0f);

    for (int it = 0; it < D_/32; it++){
        int k0 = it * 32;
        __syncthreads();
        // stage A tile (f32 -> bf16 hi/lo)
        {
            const float4* ap = (const float4*)(A + (size_t)(rowBase + ar)*D_ + k0 + ac);
            #pragma unroll
            for (int j = 0; j < 4; j++){
                float4 v = ap[j];
                __nv_bfloat16 h0=__float2bfloat16(v.x), h1=__float2bfloat16(v.y);
                __nv_bfloat16 h2=__float2bfloat16(v.z), h3=__float2bfloat16(v.w);
                __nv_bfloat16 l0=__float2bfloat16(v.x-__bfloat162float(h0));
                __nv_bfloat16 l1=__float2bfloat16(v.y-__bfloat162float(h1));
                __nv_bfloat16 l2=__float2bfloat16(v.z-__bfloat162float(h2));
                __nv_bfloat16 l3=__float2bfloat16(v.w-__bfloat162float(h3));
                int c = ac + j*4;
                *(__nv_bfloat162*)&sAh[ar][c]   = __halves2bfloat162(h0,h1);
                *(__nv_bfloat162*)&sAh[ar][c+2] = __halves2bfloat162(h2,h3);
                *(__nv_bfloat162*)&sAl[ar][c]   = __halves2bfloat162(l0,l1);
                *(__nv_bfloat162*)&sAl[ar][c+2] = __halves2bfloat162(l2,l3);
            }
        }
        // stage W tile (f32 -> bf16 hi/lo); W row-major [K][N], stride D_
        {
            const float4* wp = (const float4*)(W + (size_t)(k0 + wr)*D_ + colBase + wc);
            #pragma unroll
            for (int j = 0; j < 4; j++){
                float4 v = wp[j];
                __nv_bfloat16 h0=__float2bfloat16(v.x), h1=__float2bfloat16(v.y);
                __nv_bfloat16 h2=__float2bfloat16(v.z), h3=__float2bfloat16(v.w);
                __nv_bfloat16 l0=__float2bfloat16(v.x-__bfloat162float(h0));
                __nv_bfloat16 l1=__float2bfloat16(v.y-__bfloat162float(h1));
                __nv_bfloat16 l2=__float2bfloat16(v.z-__bfloat162float(h2));
                __nv_bfloat16 l3=__float2bfloat16(v.w-__bfloat162float(h3));
                int c = wc + j*4;
                *(__nv_bfloat162*)&sWh[wr][c]   = __halves2bfloat162(h0,h1);
                *(__nv_bfloat162*)&sWh[wr][c+2] = __halves2bfloat162(h2,h3);
                *(__nv_bfloat162*)&sWl[wr][c]   = __halves2bfloat162(l0,l1);
                *(__nv_bfloat162*)&sWl[wr][c+2] = __halves2bfloat162(l2,l3);
            }
        }
        __syncthreads();
        #pragma unroll
        for (int ks = 0; ks < 2; ks++){
            wmma::fragment<wmma::matrix_a,16,16,16,__nv_bfloat16,wmma::row_major> ah[4], al[4];
            wmma::fragment<wmma::matrix_b,16,16,16,__nv_bfloat16,wmma::row_major> bh[2], bl[2];
            #pragma unroll
            for (int mi = 0; mi < 4; mi++){
                wmma::load_matrix_sync(ah[mi], &sAh[wm + mi*16][ks*16], 40);
                wmma::load_matrix_sync(al[mi], &sAl[wm + mi*16][ks*16], 40);
            }
            #pragma unroll
            for (int nj = 0; nj < 2; nj++){
                wmma::load_matrix_sync(bh[nj], &sWh[ks*16][wn + nj*16], 136);
                wmma::load_matrix_sync(bl[nj], &sWl[ks*16][wn + nj*16], 136);
            }
            #pragma unroll
            for (int mi = 0; mi < 4; mi++)
                #pragma unroll
                for (int nj = 0; nj < 2; nj++){
                    wmma::mma_sync(cf[mi][nj], ah[mi], bh[nj], cf[mi][nj]);
                    wmma::mma_sync(cf[mi][nj], ah[mi], bl[nj], cf[mi][nj]);
                    wmma::mma_sync(cf[mi][nj], al[mi], bh[nj], cf[mi][nj]);
                }
        }
    }

    // epilogue: each warp stores 8 16x16 tiles
    #pragma unroll
    for (int mi = 0; mi < 4; mi++){
        #pragma unroll
        for (int nj = 0; nj < 2; nj++){
            int r = rowBase + wm + mi*16;
            int cc = colBase + wn + nj*16;
            if (JOB == 3){
                wmma::store_matrix_sync(Cout + (size_t)r * D_ + cc, cf[mi][nj], D_, wmma::mem_row_major);
            } else {
                float* Dst = (JOB==0) ? &g_q[0] : (JOB==1) ? &g_k[0] : &g_v[0];
                #pragma unroll
                for (int e = 0; e < cf[mi][nj].num_elements; e++){
                    float x = cf[mi][nj].x[e];
                    cf[mi][nj].x[e] = x * sigm(x);
                }
                int b = r >> 12, l0 = r & (L_-1);
                int h = cc >> 6, d0 = cc & 63;
                float* p = Dst + (((size_t)(b*H_ + h)*L_ + l0) << 6) + d0;
                wmma::store_matrix_sync(p, cf[mi][nj], 64, wmma::mem_row_major);
            }
        }
    }
}

// ---------------- gate projections (round-2 proven) ----------------
__global__ __launch_bounds__(256) void gates_kernel(const float* __restrict__ x,
                                                    const float* __restrict__ fdb,
                                                    const float* __restrict__ sdb){
    __shared__ float xs[GTOK_][D_];
    int t0 = blockIdx.x * GTOK_;
    for(int i = threadIdx.x; i < GTOK_*D_/4; i += 256)
        ((float4*)&xs[0][0])[i] = ((const float4*)(x + (size_t)t0 * D_))[i];
    __syncthreads();
    int warp = threadIdx.x >> 5, lane = threadIdx.x & 31;
    for(int o = warp; o < 80; o += 8){
        int g = o >> 4, h = o & 15;
        const float* Wt = &g_WT[o*D_];
        float wreg[32];
        #pragma unroll
        for(int j=0;j<32;j++) wreg[j] = Wt[j*32 + lane];
        float accv[GTOK_];
        #pragma unroll
        for(int tt=0;tt<GTOK_;tt++) accv[tt]=0.f;
        #pragma unroll
        for(int j=0;j<32;j++){
            float w = wreg[j];
            #pragma unroll
            for(int tt=0;tt<GTOK_;tt++) accv[tt] += xs[tt][j*32+lane] * w;
        }
        #pragma unroll
        for(int tt=0;tt<GTOK_;tt++){
            float s = accv[tt];
            #pragma unroll
            for(int off=16;off;off>>=1) s += __shfl_xor_sync(0xffffffffu, s, off);
            if(lane == 0){
                int t = t0 + tt, b = t >> 12, l = t & (L_-1);
                float bias = (g==1)?fdb[h] : (g==2)?sdb[h] : 0.f;
                float val = sigm(s + bias);
                int idx = (b*H_ + h)*L_ + l;
                if(g==0) g_beta[idx]=val; else if(g==1) g_fd[idx]=val;
                else if(g==2) g_sd[idx]=val; else if(g==3) g_fg[idx]=val;
                else g_sg[idx]=val;
            }
        }
    }
}

// ---------------- per-token prep (round-2 proven) ----------------
__global__ __launch_bounds__(128) void prep_kernel(){
    __shared__ float fw[CH_], sw[CH_];
    int bh = blockIdx.x >> 5, c = blockIdx.x & 31;
    int t = threadIdx.x;
    int gidx = bh*L_ + c*CH_ + t;
    size_t base = (size_t)gidx * HD_;
    float beta = g_beta[gidx];

    float kv=0.f, kk=0.f, vv=0.f;
    #pragma unroll 4
    for(int d4=0; d4<HD_/4; d4++){
        float4 k4 = *(const float4*)(g_k + base + d4*4);
        float4 v4 = *(const float4*)(g_v + base + d4*4);
        kv += k4.x*v4.x + k4.y*v4.y + k4.z*v4.z + k4.w*v4.w;
        kk += k4.x*k4.x + k4.y*k4.y + k4.z*k4.z + k4.w*k4.w;
        vv += v4.x*v4.x + v4.y*v4.y + v4.z*v4.z + v4.w*v4.w;
    }
    float b2 = beta*beta;
    float nk = sqrtf(kk*b2) + 1e-8f;
    float nv = sqrtf(vv*b2) + 1e-8f;
    float psi_raw = fabsf(kv*b2) / (nk*nv);
    float psi  = sigm(3.0f * psi_raw);
    float surp = sigm(10.0f * (psi - 0.5f));
    g_psi[gidx] = psi;
    fw[t] = g_fd[gidx] * (1.0f - 0.10f*psi);
    sw[t] = g_sd[gidx] * (1.0f - 0.05f*psi);

    #pragma unroll 4
    for(int d4=0; d4<HD_/4; d4++){
        float4 k4 = *(const float4*)(g_k + base + d4*4);
        float4 v4 = *(const float4*)(g_v + base + d4*4);
        k4.x*=beta; k4.y*=beta; k4.z*=beta; k4.w*=beta;
        v4.x*=beta; v4.y*=beta; v4.z*=beta; v4.w*=beta;
        *(float4*)(g_k + base + d4*4) = k4;
        *(float4*)(g_v + base + d4*4) = v4;
        float4 k5 = make_float4(k4.x*surp,k4.y*surp,k4.z*surp,k4.w*surp);
        float4 v5 = make_float4(v4.x*surp,v4.y*surp,v4.z*surp,v4.w*surp);
        *(float4*)(g_ks + base + d4*4) = k5;
        *(float4*)(g_vs + base + d4*4) = v5;
    }
    __syncthreads();
    for(int off=64; off; off>>=1){
        if(t < off){ fw[t] += fw[t+off]; sw[t] += sw[t+off]; }
        __syncthreads();
    }
    if(t == 0){
        g_dff[blockIdx.x] = powf(fw[0] * (1.0f/CH_), (float)CH_);
        g_dfs[blockIdx.x] = powf(sw[0] * (1.0f/CH_), (float)CH_);
    }
}

// ---------------- serial state scan (round-2 proven) ----------------
__global__ __launch_bounds__(256) void scan_kernel(){
    __shared__ float ksm[64][HD_];
    __shared__ float vsm[64][HD_];
    int pass = blockIdx.x >> 5, bh = blockIdx.x & 31;
    const float* kp  = pass ? &g_ks[0] : &g_k[0];
    const float* vp  = pass ? &g_vs[0] : &g_v[0];
    const float* dfp = pass ? &g_dfs[0] : &g_dff[0];
    int tid = threadIdx.x, ty = tid >> 4, tx = tid & 15;
    float st[4][4];
    #pragma unroll
    for(int i=0;i<4;i++)
        #pragma unroll
        for(int j=0;j<4;j++) st[i][j]=0.f;
    float* outp = &g_state[0] + (size_t)blockIdx.x * NCH_ * (HD_*HD_);

    for(int c = 0; c < NCH_; c++){
        float df = dfp[bh*NCH_ + c];
        #pragma unroll
        for(int i=0;i<4;i++)
            #pragma unroll
            for(int j=0;j<4;j++) st[i][j] *= df;
        #pragma unroll 1
        for(int half = 0; half < 2; half++){
            size_t base = ((size_t)bh*L_ + c*CH_ + half*64) * HD_;
            __syncthreads();
            for(int i = tid; i < 64*HD_/4; i += 256){
                ((float4*)&ksm[0][0])[i] = ((const float4*)(kp + base))[i];
                ((float4*)&vsm[0][0])[i] = ((const float4*)(vp + base))[i];
            }
            __syncthreads();
            #pragma unroll 4
            for(int l = 0; l < 64; l++){
                float4 v4 = *(float4*)&vsm[l][ty*4];
                float4 k4 = *(float4*)&ksm[l][tx*4];
                st[0][0]+=v4.x*k4.x; st[0][1]+=v4.x*k4.y; st[0][2]+=v4.x*k4.z; st[0][3]+=v4.x*k4.w;
                st[1][0]+=v4.y*k4.x; st[1][1]+=v4.y*k4.y; st[1][2]+=v4.y*k4.z; st[1][3]+=v4.y*k4.w;
                st[2][0]+=v4.z*k4.x; st[2][1]+=v4.z*k4.y; st[2][2]+=v4.z*k4.z; st[2][3]+=v4.z*k4.w;
                st[3][0]+=v4.w*k4.x; st[3][1]+=v4.w*k4.y; st[3][2]+=v4.w*k4.z; st[3][3]+=v4.w*k4.w;
            }
        }
        float* sp = outp + (size_t)c * (HD_*HD_);
        #pragma unroll
        for(int i=0;i<4;i++)
            *(float4*)(sp + (ty*4+i)*HD_ + tx*4) =
                make_float4(st[i][0], st[i][1], st[i][2], st[i][3]);
    }
}

// ---------------- per-chunk output + gated combine (round-2 proven) ----------------
__global__ __launch_bounds__(256) void o_kernel(){
    __shared__ float qsm[CH_][HD_];
    __shared__ float stm[HD_][HD_];
    int bh = blockIdx.x >> 5, c = blockIdx.x & 31;
    int b = bh >> 4, h = bh & 15;
    int tid = threadIdx.x, ly = tid >> 4, dx = tid & 15;
    size_t qbase = ((size_t)bh*L_ + c*CH_) * HD_;
    for(int i = tid; i < CH_*HD_/4; i += 256)
        ((float4*)&qsm[0][0])[i] = ((const float4*)(&g_q[0] + qbase))[i];

    float accf[8][4], accs[8][4];
    {
        size_t sb = ((size_t)bh*NCH_ + c) * (HD_*HD_);
        for(int i = tid; i < HD_*HD_/4; i += 256)
            ((float4*)&stm[0][0])[i] = ((const float4*)(&g_state[0] + sb))[i];
        __syncthreads();
        #pragma unroll
        for(int i=0;i<8;i++){ accf[i][0]=0;accf[i][1]=0;accf[i][2]=0;accf[i][3]=0; }
        for(int d = 0; d < HD_; d++){
            float4 s4 = *(float4*)&stm[d][dx*4];
            #pragma unroll
            for(int i=0;i<8;i++){
                float qv = qsm[ly*8+i][d];
                accf[i][0]+=qv*s4.x; accf[i][1]+=qv*s4.y;
                accf[i][2]+=qv*s4.z; accf[i][3]+=qv*s4.w;
            }
        }
        __syncthreads();
    }
    {
        size_t sb = ((size_t)(BH_ + bh)*NCH_ + c) * (HD_*HD_);
        for(int i = tid; i < HD_*HD_/4; i += 256)
            ((float4*)&stm[0][0])[i] = ((const float4*)(&g_state[0] + sb))[i];
        __syncthreads();
        #pragma unroll
        for(int i=0;i<8;i++){ accs[i][0]=0;accs[i][1]=0;accs[i][2]=0;accs[i][3]=0; }
        for(int d = 0; d < HD_; d++){
            float4 s4 = *(float4*)&stm[d][dx*4];
            #pragma unroll
            for(int i=0;i<8;i++){
                float qv = qsm[ly*8+i][d];
                accs[i][0]+=qv*s4.x; accs[i][1]+=qv*s4.y;
                accs[i][2]+=qv*s4.z; accs[i][3]+=qv*s4.w;
            }
        }
    }
    #pragma unroll
    for(int i=0;i<8;i++){
        int l = ly*8 + i;
        int gidx = bh*L_ + c*CH_ + l;
        float psi = g_psi[gidx];
        float a   = 0.5f + 0.3f*psi;
        float fa  = a * g_fg[gidx];
        float sa  = (1.0f - a) * g_sg[gidx];
        float4 o;
        o.x = fa*accf[i][0] + sa*accs[i][0];
        o.y = fa*accf[i][1] + sa*accs[i][1];
        o.z = fa*accf[i][2] + sa*accs[i][2];
        o.w = fa*accf[i][3] + sa*accs[i][3];
        *(float4*)(&g_oc[0] + ((size_t)(b*L_ + c*CH_ + l))*D_ + h*HD_ + dx*4) = o;
    }
}

// ---------------- launch ----------------
extern "C" void kernel_launch(void* const* d_in, const int* in_sizes, int n_in,
                              void* d_out, int out_size){
    const float* x   = (const float*)d_in[0];
    const float* Wq  = (const float*)d_in[1];
    const float* Wk  = (const float*)d_in[2];
    const float* Wv  = (const float*)d_in[3];
    const float* Wb  = (const float*)d_in[4];
    const float* Wfd = (const float*)d_in[5];
    const float* fdb = (const float*)d_in[6];
    const float* Wsd = (const float*)d_in[7];
    const float* sdb = (const float*)d_in[8];
    const float* Wfg = (const float*)d_in[9];
    const float* Wsg = (const float*)d_in[10];
    const float* Wo  = (const float*)d_in[11];
    float* out = (float*)d_out;

    dim3 tg(D_/128, TOK_/128);           // (8, 64)

    wt_kernel<<<80, 256>>>(Wb, Wfd, Wsd, Wfg, Wsg);
    wgemm_kernel<0><<<tg, 256>>>(x, Wq, nullptr);   // q = silu(x@Wq)
    wgemm_kernel<1><<<tg, 256>>>(x, Wk, nullptr);   // k
    wgemm_kernel<2><<<tg, 256>>>(x, Wv, nullptr);   // v
    gates_kernel<<<TOK_/GTOK_, 256>>>(x, fdb, sdb);
    prep_kernel<<<BH_*NCH_, 128>>>();
    scan_kernel<<<2*BH_, 256>>>();
    o_kernel<<<BH_*NCH_, 256>>>();
    wgemm_kernel<3><<<tg, 256>>>(nullptr, Wo, out); // out = oc @ Wo
}

// round 7
// speedup vs baseline: 1.8094x; 1.3795x over previous
#include <cuda_runtime.h>
#include <cuda_bf16.h>
#include <mma.h>
#include <math.h>
#include <stdint.h>

using namespace nvcuda;

#define B_   2
#define L_   4096
#define D_   1024
#define H_   16
#define HD_  64
#define CH_  128
#define NCH_ 32
#define BH_  32
#define TOK_ 8192
#define GTOK_ 8
#define NIT_ 64          // D_/16

// ---------------- scratch (device globals; no allocation) ----------------
__device__ float g_q [BH_*L_*HD_];
__device__ float g_k [BH_*L_*HD_];
__device__ float g_v [BH_*L_*HD_];
__device__ float g_ks[BH_*L_*HD_];
__device__ float g_vs[BH_*L_*HD_];
__device__ float g_state[2*BH_*NCH_*HD_*HD_];
__device__ float g_oc[TOK_*D_];
__device__ float g_beta[BH_*L_];
__device__ float g_fd [BH_*L_];
__device__ float g_sd [BH_*L_];
__device__ float g_fg [BH_*L_];
__device__ float g_sg [BH_*L_];
__device__ float g_psi[BH_*L_];
__device__ float g_dff[BH_*NCH_];
__device__ float g_dfs[BH_*NCH_];
__device__ float g_WT [80*D_];

__device__ __forceinline__ float sigm(float x){ return 1.0f/(1.0f+expf(-x)); }

// convert 8 floats (2 float4) -> packed hi uint4 + lo uint4 (8 bf16 each)
__device__ __forceinline__ void cvt8(const float4& a, const float4& b, uint4& H, uint4& Lo){
    __nv_bfloat16 h0=__float2bfloat16(a.x), h1=__float2bfloat16(a.y);
    __nv_bfloat16 h2=__float2bfloat16(a.z), h3=__float2bfloat16(a.w);
    __nv_bfloat16 h4=__float2bfloat16(b.x), h5=__float2bfloat16(b.y);
    __nv_bfloat16 h6=__float2bfloat16(b.z), h7=__float2bfloat16(b.w);
    __nv_bfloat162 p0=__halves2bfloat162(h0,h1), p1=__halves2bfloat162(h2,h3);
    __nv_bfloat162 p2=__halves2bfloat162(h4,h5), p3=__halves2bfloat162(h6,h7);
    H.x=*(uint32_t*)&p0; H.y=*(uint32_t*)&p1; H.z=*(uint32_t*)&p2; H.w=*(uint32_t*)&p3;
    __nv_bfloat16 l0=__float2bfloat16(a.x-__bfloat162float(h0));
    __nv_bfloat16 l1=__float2bfloat16(a.y-__bfloat162float(h1));
    __nv_bfloat16 l2=__float2bfloat16(a.z-__bfloat162float(h2));
    __nv_bfloat16 l3=__float2bfloat16(a.w-__bfloat162float(h3));
    __nv_bfloat16 l4=__float2bfloat16(b.x-__bfloat162float(h4));
    __nv_bfloat16 l5=__float2bfloat16(b.y-__bfloat162float(h5));
    __nv_bfloat16 l6=__float2bfloat16(b.z-__bfloat162float(h6));
    __nv_bfloat16 l7=__float2bfloat16(b.w-__bfloat162float(h7));
    __nv_bfloat162 q0=__halves2bfloat162(l0,l1), q1=__halves2bfloat162(l2,l3);
    __nv_bfloat162 q2=__halves2bfloat162(l4,l5), q3=__halves2bfloat162(l6,l7);
    Lo.x=*(uint32_t*)&q0; Lo.y=*(uint32_t*)&q1; Lo.z=*(uint32_t*)&q2; Lo.w=*(uint32_t*)&q3;
}

// ---------------- transpose gate weights ----------------
__global__ void wt_kernel(const float* __restrict__ Wb,  const float* __restrict__ Wfd,
                          const float* __restrict__ Wsd, const float* __restrict__ Wfg,
                          const float* __restrict__ Wsg){
    int o = blockIdx.x;
    int g = o >> 4, h = o & 15;
    const float* W = (g==0)?Wb:(g==1)?Wfd:(g==2)?Wsd:(g==3)?Wfg:Wsg;
    for(int i = threadIdx.x; i < D_; i += blockDim.x)
        g_WT[o*D_ + i] = W[i*H_ + h];
}

// ---------------- WMMA bf16 split-GEMM, double-buffered + reg-prefetch ----------------
// C[8192x1024] = A(f32) @ W(f32); acc += Ah*Wh + Ah*Wl + Al*Wh.
// 128x128 tile/CTA, BK=16, 2-stage smem (static 41984B), 8 warps of 64x32.
template<int JOB>
__global__ __launch_bounds__(256) void wgemm_kernel(const float* __restrict__ Ain,
                                                    const float* __restrict__ W,
                                                    float* __restrict__ Cout){
    __shared__ __align__(16) __nv_bfloat16 sAh[2][128][24];   // 2*6144 B
    __shared__ __align__(16) __nv_bfloat16 sAl[2][128][24];
    __shared__ __align__(16) __nv_bfloat16 sWh[2][16][136];   // 2*4352 B
    __shared__ __align__(16) __nv_bfloat16 sWl[2][16][136];
    const float* A = (JOB==3) ? &g_oc[0] : Ain;

    int tid = threadIdx.x, warp = tid >> 5;
    int wm = (warp >> 2) * 64, wn = (warp & 3) * 32;
    int rowBase = blockIdx.y * 128, colBase = blockIdx.x * 128;

    // staging coords: A: row ar, 8 floats at k-offset ac; W: k-row wr, 8 floats at col wc
    int ar = tid >> 1,  ac = (tid & 1) * 8;
    int wr = tid >> 4,  wc = (tid & 15) * 8;
    const float* apb = A + (size_t)(rowBase + ar)*D_ + ac;
    const float* wpb = W + (size_t)wr*D_ + colBase + wc;

    wmma::fragment<wmma::accumulator,16,16,16,float> cf[4][2];
    #pragma unroll
    for(int mi=0;mi<4;mi++)
        #pragma unroll
        for(int nj=0;nj<2;nj++) wmma::fill_fragment(cf[mi][nj], 0.0f);

    // prologue: stage it=0 into buf 0
    {
        float4 a0 = *(const float4*)(apb + 0), a1 = *(const float4*)(apb + 4);
        float4 w0 = *(const float4*)(wpb + 0), w1 = *(const float4*)(wpb + 4);
        uint4 H, Lo;
        cvt8(a0, a1, H, Lo);
        *(uint4*)&sAh[0][ar][ac] = H;  *(uint4*)&sAl[0][ar][ac] = Lo;
        cvt8(w0, w1, H, Lo);
        *(uint4*)&sWh[0][wr][wc] = H;  *(uint4*)&sWl[0][wr][wc] = Lo;
    }
    __syncthreads();

    for (int it = 0; it < NIT_; it++){
        int buf = it & 1;
        float4 a0, a1, w0, w1;
        if (it + 1 < NIT_){
            const float* ap = apb + (it+1)*16;
            const float* wp = wpb + (size_t)(it+1)*16*D_;
            a0 = *(const float4*)(ap + 0); a1 = *(const float4*)(ap + 4);
            w0 = *(const float4*)(wp + 0); w1 = *(const float4*)(wp + 4);
        }
        // MMA on current buffer
        {
            wmma::fragment<wmma::matrix_a,16,16,16,__nv_bfloat16,wmma::row_major> ah[4], al[4];
            wmma::fragment<wmma::matrix_b,16,16,16,__nv_bfloat16,wmma::row_major> bh[2], bl[2];
            #pragma unroll
            for (int mi = 0; mi < 4; mi++){
                wmma::load_matrix_sync(ah[mi], &sAh[buf][wm + mi*16][0], 24);
                wmma::load_matrix_sync(al[mi], &sAl[buf][wm + mi*16][0], 24);
            }
            #pragma unroll
            for (int nj = 0; nj < 2; nj++){
                wmma::load_matrix_sync(bh[nj], &sWh[buf][0][wn + nj*16], 136);
                wmma::load_matrix_sync(bl[nj], &sWl[buf][0][wn + nj*16], 136);
            }
            #pragma unroll
            for (int mi = 0; mi < 4; mi++)
                #pragma unroll
                for (int nj = 0; nj < 2; nj++){
                    wmma::mma_sync(cf[mi][nj], ah[mi], bh[nj], cf[mi][nj]);
                    wmma::mma_sync(cf[mi][nj], ah[mi], bl[nj], cf[mi][nj]);
                    wmma::mma_sync(cf[mi][nj], al[mi], bh[nj], cf[mi][nj]);
                }
        }
        if (it + 1 < NIT_){
            int nxt = buf ^ 1;
            uint4 H, Lo;
            cvt8(a0, a1, H, Lo);
            *(uint4*)&sAh[nxt][ar][ac] = H;  *(uint4*)&sAl[nxt][ar][ac] = Lo;
            cvt8(w0, w1, H, Lo);
            *(uint4*)&sWh[nxt][wr][wc] = H;  *(uint4*)&sWl[nxt][wr][wc] = Lo;
        }
        __syncthreads();
    }

    // epilogue: each warp stores 8 16x16 tiles
    #pragma unroll
    for (int mi = 0; mi < 4; mi++){
        #pragma unroll
        for (int nj = 0; nj < 2; nj++){
            int r = rowBase + wm + mi*16;
            int cc = colBase + wn + nj*16;
            if (JOB == 3){
                wmma::store_matrix_sync(Cout + (size_t)r * D_ + cc, cf[mi][nj], D_, wmma::mem_row_major);
            } else {
                float* Dst = (JOB==0) ? &g_q[0] : (JOB==1) ? &g_k[0] : &g_v[0];
                #pragma unroll
                for (int e = 0; e < cf[mi][nj].num_elements; e++){
                    float x = cf[mi][nj].x[e];
                    cf[mi][nj].x[e] = x * sigm(x);
                }
                int b = r >> 12, l0 = r & (L_-1);
                int h = cc >> 6, d0 = cc & 63;
                float* p = Dst + (((size_t)(b*H_ + h)*L_ + l0) << 6) + d0;
                wmma::store_matrix_sync(p, cf[mi][nj], 64, wmma::mem_row_major);
            }
        }
    }
}

// ---------------- gate projections (proven) ----------------
__global__ __launch_bounds__(256) void gates_kernel(const float* __restrict__ x,
                                                    const float* __restrict__ fdb,
                                                    const float* __restrict__ sdb){
    __shared__ float xs[GTOK_][D_];
    int t0 = blockIdx.x * GTOK_;
    for(int i = threadIdx.x; i < GTOK_*D_/4; i += 256)
        ((float4*)&xs[0][0])[i] = ((const float4*)(x + (size_t)t0 * D_))[i];
    __syncthreads();
    int warp = threadIdx.x >> 5, lane = threadIdx.x & 31;
    for(int o = warp; o < 80; o += 8){
        int g = o >> 4, h = o & 15;
        const float* Wt = &g_WT[o*D_];
        float wreg[32];
        #pragma unroll
        for(int j=0;j<32;j++) wreg[j] = Wt[j*32 + lane];
        float accv[GTOK_];
        #pragma unroll
        for(int tt=0;tt<GTOK_;tt++) accv[tt]=0.f;
        #pragma unroll
        for(int j=0;j<32;j++){
            float w = wreg[j];
            #pragma unroll
            for(int tt=0;tt<GTOK_;tt++) accv[tt] += xs[tt][j*32+lane] * w;
        }
        #pragma unroll
        for(int tt=0;tt<GTOK_;tt++){
            float s = accv[tt];
            #pragma unroll
            for(int off=16;off;off>>=1) s += __shfl_xor_sync(0xffffffffu, s, off);
            if(lane == 0){
                int t = t0 + tt, b = t >> 12, l = t & (L_-1);
                float bias = (g==1)?fdb[h] : (g==2)?sdb[h] : 0.f;
                float val = sigm(s + bias);
                int idx = (b*H_ + h)*L_ + l;
                if(g==0) g_beta[idx]=val; else if(g==1) g_fd[idx]=val;
                else if(g==2) g_sd[idx]=val; else if(g==3) g_fg[idx]=val;
                else g_sg[idx]=val;
            }
        }
    }
}

// ---------------- per-token prep (proven) ----------------
__global__ __launch_bounds__(128) void prep_kernel(){
    __shared__ float fw[CH_], sw[CH_];
    int bh = blockIdx.x >> 5, c = blockIdx.x & 31;
    int t = threadIdx.x;
    int gidx = bh*L_ + c*CH_ + t;
    size_t base = (size_t)gidx * HD_;
    float beta = g_beta[gidx];

    float kv=0.f, kk=0.f, vv=0.f;
    #pragma unroll 4
    for(int d4=0; d4<HD_/4; d4++){
        float4 k4 = *(const float4*)(g_k + base + d4*4);
        float4 v4 = *(const float4*)(g_v + base + d4*4);
        kv += k4.x*v4.x + k4.y*v4.y + k4.z*v4.z + k4.w*v4.w;
        kk += k4.x*k4.x + k4.y*k4.y + k4.z*k4.z + k4.w*k4.w;
        vv += v4.x*v4.x + v4.y*v4.y + v4.z*v4.z + v4.w*v4.w;
    }
    float b2 = beta*beta;
    float nk = sqrtf(kk*b2) + 1e-8f;
    float nv = sqrtf(vv*b2) + 1e-8f;
    float psi_raw = fabsf(kv*b2) / (nk*nv);
    float psi  = sigm(3.0f * psi_raw);
    float surp = sigm(10.0f * (psi - 0.5f));
    g_psi[gidx] = psi;
    fw[t] = g_fd[gidx] * (1.0f - 0.10f*psi);
    sw[t] = g_sd[gidx] * (1.0f - 0.05f*psi);

    #pragma unroll 4
    for(int d4=0; d4<HD_/4; d4++){
        float4 k4 = *(const float4*)(g_k + base + d4*4);
        float4 v4 = *(const float4*)(g_v + base + d4*4);
        k4.x*=beta; k4.y*=beta; k4.z*=beta; k4.w*=beta;
        v4.x*=beta; v4.y*=beta; v4.z*=beta; v4.w*=beta;
        *(float4*)(g_k + base + d4*4) = k4;
        *(float4*)(g_v + base + d4*4) = v4;
        float4 k5 = make_float4(k4.x*surp,k4.y*surp,k4.z*surp,k4.w*surp);
        float4 v5 = make_float4(v4.x*surp,v4.y*surp,v4.z*surp,v4.w*surp);
        *(float4*)(g_ks + base + d4*4) = k5;
        *(float4*)(g_vs + base + d4*4) = v5;
    }
    __syncthreads();
    for(int off=64; off; off>>=1){
        if(t < off){ fw[t] += fw[t+off]; sw[t] += sw[t+off]; }
        __syncthreads();
    }
    if(t == 0){
        g_dff[blockIdx.x] = powf(fw[0] * (1.0f/CH_), (float)CH_);
        g_dfs[blockIdx.x] = powf(sw[0] * (1.0f/CH_), (float)CH_);
    }
}

// ---------------- parallel per-chunk outer products: S_c = v^T k (2048 CTAs) ----------------
__global__ __launch_bounds__(256) void chunk_outer_kernel(){
    __shared__ float ksm[64][HD_];
    __shared__ float vsm[64][HD_];
    int bx = blockIdx.x;                 // pass*1024 + bh*32 + c
    int pass = bx >> 10, bh = (bx >> 5) & 31, c = bx & 31;
    const float* kp = pass ? &g_ks[0] : &g_k[0];
    const float* vp = pass ? &g_vs[0] : &g_v[0];
    int tid = threadIdx.x, ty = tid >> 4, tx = tid & 15;
    float st[4][4];
    #pragma unroll
    for(int i=0;i<4;i++)
        #pragma unroll
        for(int j=0;j<4;j++) st[i][j]=0.f;

    #pragma unroll 1
    for(int half = 0; half < 2; half++){
        size_t base = ((size_t)bh*L_ + c*CH_ + half*64) * HD_;
        __syncthreads();
        for(int i = tid; i < 64*HD_/4; i += 256){
            ((float4*)&ksm[0][0])[i] = ((const float4*)(kp + base))[i];
            ((float4*)&vsm[0][0])[i] = ((const float4*)(vp + base))[i];
        }
        __syncthreads();
        #pragma unroll 4
        for(int l = 0; l < 64; l++){
            float4 v4 = *(float4*)&vsm[l][ty*4];
            float4 k4 = *(float4*)&ksm[l][tx*4];
            st[0][0]+=v4.x*k4.x; st[0][1]+=v4.x*k4.y; st[0][2]+=v4.x*k4.z; st[0][3]+=v4.x*k4.w;
            st[1][0]+=v4.y*k4.x; st[1][1]+=v4.y*k4.y; st[1][2]+=v4.y*k4.z; st[1][3]+=v4.y*k4.w;
            st[2][0]+=v4.z*k4.x; st[2][1]+=v4.z*k4.y; st[2][2]+=v4.z*k4.z; st[2][3]+=v4.z*k4.w;
            st[3][0]+=v4.w*k4.x; st[3][1]+=v4.w*k4.y; st[3][2]+=v4.w*k4.z; st[3][3]+=v4.w*k4.w;
        }
    }
    float* sp = &g_state[0] + (size_t)((pass*BH_ + bh)*NCH_ + c) * (HD_*HD_);
    #pragma unroll
    for(int i=0;i<4;i++)
        *(float4*)(sp + (ty*4+i)*HD_ + tx*4) =
            make_float4(st[i][0], st[i][1], st[i][2], st[i][3]);
}

// ---------------- serial recurrence in-place: state_c = df_c*state_{c-1} + S_c ----------------
__global__ __launch_bounds__(256) void scan2_kernel(){
    int pass = blockIdx.x >> 5, bh = blockIdx.x & 31;
    const float* dfp = pass ? &g_dfs[0] : &g_dff[0];
    float* base = &g_state[0] + (size_t)blockIdx.x * NCH_ * (HD_*HD_);
    int off = threadIdx.x * 16;
    float4 st0 = make_float4(0,0,0,0), st1 = st0, st2 = st0, st3 = st0;
    for(int c = 0; c < NCH_; c++){
        float df = dfp[bh*NCH_ + c];
        float* p = base + (size_t)c * (HD_*HD_) + off;
        float4 s0 = *(float4*)(p+0), s1 = *(float4*)(p+4);
        float4 s2 = *(float4*)(p+8), s3 = *(float4*)(p+12);
        st0.x = st0.x*df + s0.x; st0.y = st0.y*df + s0.y; st0.z = st0.z*df + s0.z; st0.w = st0.w*df + s0.w;
        st1.x = st1.x*df + s1.x; st1.y = st1.y*df + s1.y; st1.z = st1.z*df + s1.z; st1.w = st1.w*df + s1.w;
        st2.x = st2.x*df + s2.x; st2.y = st2.y*df + s2.y; st2.z = st2.z*df + s2.z; st2.w = st2.w*df + s2.w;
        st3.x = st3.x*df + s3.x; st3.y = st3.y*df + s3.y; st3.z = st3.z*df + s3.z; st3.w = st3.w*df + s3.w;
        *(float4*)(p+0) = st0; *(float4*)(p+4) = st1;
        *(float4*)(p+8) = st2; *(float4*)(p+12) = st3;
    }
}

// ---------------- per-chunk output + gated combine (proven) ----------------
__global__ __launch_bounds__(256) void o_kernel(){
    __shared__ float qsm[CH_][HD_];
    __shared__ float stm[HD_][HD_];
    int bh = blockIdx.x >> 5, c = blockIdx.x & 31;
    int b = bh >> 4, h = bh & 15;
    int tid = threadIdx.x, ly = tid >> 4, dx = tid & 15;
    size_t qbase = ((size_t)bh*L_ + c*CH_) * HD_;
    for(int i = tid; i < CH_*HD_/4; i += 256)
        ((float4*)&qsm[0][0])[i] = ((const float4*)(&g_q[0] + qbase))[i];

    float accf[8][4], accs[8][4];
    {
        size_t sb = ((size_t)bh*NCH_ + c) * (HD_*HD_);
        for(int i = tid; i < HD_*HD_/4; i += 256)
            ((float4*)&stm[0][0])[i] = ((const float4*)(&g_state[0] + sb))[i];
        __syncthreads();
        #pragma unroll
        for(int i=0;i<8;i++){ accf[i][0]=0;accf[i][1]=0;accf[i][2]=0;accf[i][3]=0; }
        for(int d = 0; d < HD_; d++){
            float4 s4 = *(float4*)&stm[d][dx*4];
            #pragma unroll
            for(int i=0;i<8;i++){
                float qv = qsm[ly*8+i][d];
                accf[i][0]+=qv*s4.x; accf[i][1]+=qv*s4.y;
                accf[i][2]+=qv*s4.z; accf[i][3]+=qv*s4.w;
            }
        }
        __syncthreads();
    }
    {
        size_t sb = ((size_t)(BH_ + bh)*NCH_ + c) * (HD_*HD_);
        for(int i = tid; i < HD_*HD_/4; i += 256)
            ((float4*)&stm[0][0])[i] = ((const float4*)(&g_state[0] + sb))[i];
        __syncthreads();
        #pragma unroll
        for(int i=0;i<8;i++){ accs[i][0]=0;accs[i][1]=0;accs[i][2]=0;accs[i][3]=0; }
        for(int d = 0; d < HD_; d++){
            float4 s4 = *(float4*)&stm[d][dx*4];
            #pragma unroll
            for(int i=0;i<8;i++){
                float qv = qsm[ly*8+i][d];
                accs[i][0]+=qv*s4.x; accs[i][1]+=qv*s4.y;
                accs[i][2]+=qv*s4.z; accs[i][3]+=qv*s4.w;
            }
        }
    }
    #pragma unroll
    for(int i=0;i<8;i++){
        int l = ly*8 + i;
        int gidx = bh*L_ + c*CH_ + l;
        float psi = g_psi[gidx];
        float a   = 0.5f + 0.3f*psi;
        float fa  = a * g_fg[gidx];
        float sa  = (1.0f - a) * g_sg[gidx];
        float4 o;
        o.x = fa*accf[i][0] + sa*accs[i][0];
        o.y = fa*accf[i][1] + sa*accs[i][1];
        o.z = fa*accf[i][2] + sa*accs[i][2];
        o.w = fa*accf[i][3] + sa*accs[i][3];
        *(float4*)(&g_oc[0] + ((size_t)(b*L_ + c*CH_ + l))*D_ + h*HD_ + dx*4) = o;
    }
}

// ---------------- launch ----------------
extern "C" void kernel_launch(void* const* d_in, const int* in_sizes, int n_in,
                              void* d_out, int out_size){
    const float* x   = (const float*)d_in[0];
    const float* Wq  = (const float*)d_in[1];
    const float* Wk  = (const float*)d_in[2];
    const float* Wv  = (const float*)d_in[3];
    const float* Wb  = (const float*)d_in[4];
    const float* Wfd = (const float*)d_in[5];
    const float* fdb = (const float*)d_in[6];
    const float* Wsd = (const float*)d_in[7];
    const float* sdb = (const float*)d_in[8];
    const float* Wfg = (const float*)d_in[9];
    const float* Wsg = (const float*)d_in[10];
    const float* Wo  = (const float*)d_in[11];
    float* out = (float*)d_out;

    dim3 tg(D_/128, TOK_/128);           // (8, 64)

    wt_kernel<<<80, 256>>>(Wb, Wfd, Wsd, Wfg, Wsg);
    wgemm_kernel<0><<<tg, 256>>>(x, Wq, nullptr);   // q = silu(x@Wq)
    wgemm_kernel<1><<<tg, 256>>>(x, Wk, nullptr);   // k
    wgemm_kernel<2><<<tg, 256>>>(x, Wv, nullptr);   // v
    gates_kernel<<<TOK_/GTOK_, 256>>>(x, fdb, sdb);
    prep_kernel<<<BH_*NCH_, 128>>>();
    chunk_outer_kernel<<<2*BH_*NCH_, 256>>>();
    scan2_kernel<<<2*BH_, 256>>>();
    o_kernel<<<BH_*NCH_, 256>>>();
    wgemm_kernel<3><<<tg, 256>>>(nullptr, Wo, out); // out = oc @ Wo
}